// round 5
// baseline (speedup 1.0000x reference)
#include <cuda_runtime.h>
#include <cstdint>

#define NN       8192
#define THREADS  512
#define VEC      4                   // float4 chunks per thread per row
#define NWARPS   (THREADS/32)
#define STAGES   3
#define STAGE_BYTES (NN * 4)         // 32 KiB per staged row
#define SMEM_DYN (STAGES * STAGE_BYTES)
#define GBLOCKS  296                 // 2 blocks * 148 SMs

__device__ float g_zero = 0.0f;

__device__ __forceinline__ uint32_t sw128(uint32_t off)
{
    return off ^ ((off >> 3) & 0x70);
}

#define CP_ASYNC16(dst_u32, src_ptr) \
    asm volatile("cp.async.cg.shared.global [%0], [%1], 16;" \
                 :: "r"(dst_u32), "l"(src_ptr))
#define CP_COMMIT() asm volatile("cp.async.commit_group;")
#define CP_WAIT2()  asm volatile("cp.async.wait_group 2;" ::: "memory")

// ---------------------------------------------------------------------------
// Persistent kernel: 3-stage cp.async smem pipeline over rows.
// Each block first recomputes cb = cumsum(bary) into registers (overlapped
// with the prologue copies), then loops: wait stage -> LDS -> thread scan ->
// one-barrier block scan -> |ca - cb| accumulate. One atomicAdd per block.
// ---------------------------------------------------------------------------
__global__ void __launch_bounds__(THREADS, 2)
row_w1_kernel(const float* __restrict__ x, const float* __restrict__ bary,
              float* __restrict__ out, int D)
{
    extern __shared__ float sbuf[];          // STAGES * NN floats
    __shared__ float ws[2][NWARPS];
    __shared__ float red[NWARPS];

    const int t    = threadIdx.x;
    const int lane = t & 31;
    const int wid  = t >> 5;
    const int G    = gridDim.x;

    const uint32_t sbase = (uint32_t)__cvta_generic_to_shared(sbuf);

    // swizzled per-thread byte offsets within a stage (idx = 4t + i)
    const uint32_t o0 = sw128((uint32_t)(t * 4 + 0) * 16);
    const uint32_t o1 = sw128((uint32_t)(t * 4 + 1) * 16);
    const uint32_t o2 = sw128((uint32_t)(t * 4 + 2) * 16);
    const uint32_t o3 = sw128((uint32_t)(t * 4 + 3) * 16);

    uint32_t s0 = sbase;                     // rotating stage bases
    uint32_t s1 = sbase + STAGE_BYTES;
    uint32_t s2 = sbase + 2 * STAGE_BYTES;

    const float4* xb = reinterpret_cast<const float4*>(x);

    // ---- prologue: issue copies for rows b and b+G ----
    int row = blockIdx.x;                    // row < D (grid <= D)
    {
        const float4* p = xb + (size_t)row * (NN / 4) + t * VEC;
        CP_ASYNC16(s0 + o0, p + 0);
        CP_ASYNC16(s0 + o1, p + 1);
        CP_ASYNC16(s0 + o2, p + 2);
        CP_ASYNC16(s0 + o3, p + 3);
    }
    CP_COMMIT();
    if (row + G < D) {
        const float4* p = xb + (size_t)(row + G) * (NN / 4) + t * VEC;
        CP_ASYNC16(s1 + o0, p + 0);
        CP_ASYNC16(s1 + o1, p + 1);
        CP_ASYNC16(s1 + o2, p + 2);
        CP_ASYNC16(s1 + o3, p + 3);
    }
    CP_COMMIT();

    // ---- recompute cb = cumsum(bary) for this thread's 16 columns ----
    float4 cb0, cb1, cb2, cb3;
    {
        const float4* bp = reinterpret_cast<const float4*>(bary) + t * VEC;
        float4 b0 = bp[0], b1 = bp[1], b2 = bp[2], b3 = bp[3];

        float p00 = b0.x;
        float p01 = p00 + b0.y;
        float p02 = p01 + b0.z;
        float p03 = p02 + b0.w;
        float p04 = p03 + b1.x;
        float p05 = p04 + b1.y;
        float p06 = p05 + b1.z;
        float p07 = p06 + b1.w;
        float p08 = p07 + b2.x;
        float p09 = p08 + b2.y;
        float p10 = p09 + b2.z;
        float p11 = p10 + b2.w;
        float p12 = p11 + b3.x;
        float p13 = p12 + b3.y;
        float p14 = p13 + b3.z;
        float p15 = p14 + b3.w;

        float s = p15;
        #pragma unroll
        for (int o = 1; o < 32; o <<= 1) {
            float y = __shfl_up_sync(0xFFFFFFFFu, s, o);
            if (lane >= o) s += y;
        }
        if (lane == 31) red[wid] = s;
        __syncthreads();
        float w = (lane < NWARPS) ? red[lane] : 0.0f;
        #pragma unroll
        for (int o = 1; o < NWARPS; o <<= 1) {
            float y = __shfl_up_sync(0xFFFFFFFFu, w, o);
            if (lane >= o) w += y;
        }
        float woff = (wid > 0) ? __shfl_sync(0xFFFFFFFFu, w, wid - 1) : 0.0f;
        float off = woff + (s - p15);

        cb0.x = off + p00;  cb0.y = off + p01;  cb0.z = off + p02;  cb0.w = off + p03;
        cb1.x = off + p04;  cb1.y = off + p05;  cb1.z = off + p06;  cb1.w = off + p07;
        cb2.x = off + p08;  cb2.y = off + p09;  cb2.z = off + p10;  cb2.w = off + p11;
        cb3.x = off + p12;  cb3.y = off + p13;  cb3.z = off + p14;  cb3.w = off + p15;
    }

    // ---- main loop ----
    float total = 0.0f;
    int it = 0;

    while (row < D) {
        // issue row+2G into the stage two ahead
        const int r2 = row + 2 * G;
        if (r2 < D) {
            const float4* p = xb + (size_t)r2 * (NN / 4) + t * VEC;
            CP_ASYNC16(s2 + o0, p + 0);
            CP_ASYNC16(s2 + o1, p + 1);
            CP_ASYNC16(s2 + o2, p + 2);
            CP_ASYNC16(s2 + o3, p + 3);
        }
        CP_COMMIT();

        CP_WAIT2();             // current stage (s0) complete for this thread
        __syncthreads();        // ... and for all threads

        // consume stage s0
        float4 v0, v1, v2, v3;
        {
            float4* q;
            q = (float4*)__cvta_shared_to_generic(s0 + o0); v0 = *q;
            q = (float4*)__cvta_shared_to_generic(s0 + o1); v1 = *q;
            q = (float4*)__cvta_shared_to_generic(s0 + o2); v2 = *q;
            q = (float4*)__cvta_shared_to_generic(s0 + o3); v3 = *q;
        }

        float l00 = v0.x;
        float l01 = l00 + v0.y;
        float l02 = l01 + v0.z;
        float l03 = l02 + v0.w;
        float l04 = l03 + v1.x;
        float l05 = l04 + v1.y;
        float l06 = l05 + v1.z;
        float l07 = l06 + v1.w;
        float l08 = l07 + v2.x;
        float l09 = l08 + v2.y;
        float l10 = l09 + v2.z;
        float l11 = l10 + v2.w;
        float l12 = l11 + v3.x;
        float l13 = l12 + v3.y;
        float l14 = l13 + v3.z;
        float l15 = l14 + v3.w;

        float s = l15;
        #pragma unroll
        for (int o = 1; o < 32; o <<= 1) {
            float y = __shfl_up_sync(0xFFFFFFFFu, s, o);
            if (lane >= o) s += y;
        }
        if (lane == 31) ws[it & 1][wid] = s;
        __syncthreads();

        float w = (lane < NWARPS) ? ws[it & 1][lane] : 0.0f;
        #pragma unroll
        for (int o = 1; o < NWARPS; o <<= 1) {
            float y = __shfl_up_sync(0xFFFFFFFFu, w, o);
            if (lane >= o) w += y;
        }
        float woff = (wid > 0) ? __shfl_sync(0xFFFFFFFFu, w, wid - 1) : 0.0f;
        float off = woff + (s - l15);   // exclusive prefix for this thread

        float acc;
        acc  = fabsf(off + l00 - cb0.x);
        acc += fabsf(off + l01 - cb0.y);
        acc += fabsf(off + l02 - cb0.z);
        acc += fabsf(off + l03 - cb0.w);
        acc += fabsf(off + l04 - cb1.x);
        acc += fabsf(off + l05 - cb1.y);
        acc += fabsf(off + l06 - cb1.z);
        acc += fabsf(off + l07 - cb1.w);
        acc += fabsf(off + l08 - cb2.x);
        acc += fabsf(off + l09 - cb2.y);
        acc += fabsf(off + l10 - cb2.z);
        acc += fabsf(off + l11 - cb2.w);
        acc += fabsf(off + l12 - cb3.x);
        acc += fabsf(off + l13 - cb3.y);
        acc += fabsf(off + l14 - cb3.z);
        if (t != THREADS - 1)               // exclude global index N-1
            acc += fabsf(off + l15 - cb3.w);

        total += acc;

        // rotate stages
        uint32_t tmp = s0; s0 = s1; s1 = s2; s2 = tmp;
        row += G; ++it;
    }

    // block reduction + one atomic per block
    #pragma unroll
    for (int o = 16; o > 0; o >>= 1)
        total += __shfl_down_sync(0xFFFFFFFFu, total, o);
    if (lane == 0) red[wid] = total;
    __syncthreads();
    if (wid == 0) {
        float v = (lane < NWARPS) ? red[lane] : 0.0f;
        #pragma unroll
        for (int o = NWARPS / 2; o > 0; o >>= 1)
            v += __shfl_down_sync(0xFFFFFFFFu, v, o);
        if (lane == 0) atomicAdd(out, v);
    }
}

// ---------------------------------------------------------------------------
extern "C" void kernel_launch(void* const* d_in, const int* in_sizes, int n_in,
                              void* d_out, int out_size)
{
    const float* x    = (const float*)d_in[0];   // [D, N] f32
    const float* bary = (const float*)d_in[1];   // [N] f32
    float* out = (float*)d_out;

    const int N = in_sizes[1];
    const int D = in_sizes[0] / N;
    (void)n_in; (void)out_size;

    // out[0] = 0 via D2D copy from a device-global zero (capturable, no alloc)
    void* zp = nullptr;
    cudaGetSymbolAddress(&zp, g_zero);
    cudaMemcpyAsync(out, zp, sizeof(float), cudaMemcpyDeviceToDevice, 0);
    // out[1..N] = bary
    cudaMemcpyAsync(out + 1, bary, (size_t)N * sizeof(float),
                    cudaMemcpyDeviceToDevice, 0);

    cudaFuncSetAttribute(row_w1_kernel,
                         cudaFuncAttributeMaxDynamicSharedMemorySize, SMEM_DYN);

    const int grid = (D < GBLOCKS) ? D : GBLOCKS;
    row_w1_kernel<<<grid, THREADS, SMEM_DYN>>>(x, bary, out, D);
}

// round 6
// speedup vs baseline: 1.4708x; 1.4708x over previous
#include <cuda_runtime.h>
#include <cstdint>

#define NN      8192
#define THREADS 512
#define VEC     4                    // float4 loads per thread per row
#define NWARPS  (THREADS/32)
#define GBLOCKS 148                  // 1 block per SM, single wave

__device__ float g_zero = 0.0f;

// ---------------------------------------------------------------------------
// Persistent kernel, 1 block/SM, depth-2 register prefetch pipeline.
// Per row: consume v (scan + one-barrier block scan + |ca-cb| acc) while
// rows row+G (w) and row+2G (u) are in flight. cb recomputed per block from
// bary (L2-hot), overlapped with the prologue loads.
// ---------------------------------------------------------------------------
__global__ void __launch_bounds__(THREADS, 1)
row_w1_kernel(const float* __restrict__ x, const float* __restrict__ bary,
              float* __restrict__ out, int D)
{
    __shared__ float ws[2][NWARPS];
    __shared__ float red[NWARPS];

    const int t    = threadIdx.x;
    const int lane = t & 31;
    const int wid  = t >> 5;
    const int G    = gridDim.x;

    const float4* xb = reinterpret_cast<const float4*>(x);

    // ---- prologue: issue loads for rows b and b+G ----
    int row = blockIdx.x;                    // grid <= D, so row < D
    float4 v0, v1, v2, v3;
    {
        const float4* p = xb + (size_t)row * (NN / 4) + t * VEC;
        v0 = p[0]; v1 = p[1]; v2 = p[2]; v3 = p[3];
    }
    float4 w0, w1, w2, w3;
    const bool wv = (row + G < D);
    if (wv) {
        const float4* p = xb + (size_t)(row + G) * (NN / 4) + t * VEC;
        w0 = p[0]; w1 = p[1]; w2 = p[2]; w3 = p[3];
    }

    // ---- cb = cumsum(bary), this thread's 16 columns (overlaps loads) ----
    float4 cb0, cb1, cb2, cb3;
    {
        const float4* bp = reinterpret_cast<const float4*>(bary) + t * VEC;
        float4 b0 = bp[0], b1 = bp[1], b2 = bp[2], b3 = bp[3];

        float p00 = b0.x;
        float p01 = p00 + b0.y;
        float p02 = p01 + b0.z;
        float p03 = p02 + b0.w;
        float p04 = p03 + b1.x;
        float p05 = p04 + b1.y;
        float p06 = p05 + b1.z;
        float p07 = p06 + b1.w;
        float p08 = p07 + b2.x;
        float p09 = p08 + b2.y;
        float p10 = p09 + b2.z;
        float p11 = p10 + b2.w;
        float p12 = p11 + b3.x;
        float p13 = p12 + b3.y;
        float p14 = p13 + b3.z;
        float p15 = p14 + b3.w;

        float s = p15;
        #pragma unroll
        for (int o = 1; o < 32; o <<= 1) {
            float y = __shfl_up_sync(0xFFFFFFFFu, s, o);
            if (lane >= o) s += y;
        }
        if (lane == 31) red[wid] = s;
        __syncthreads();
        float w = (lane < NWARPS) ? red[lane] : 0.0f;
        #pragma unroll
        for (int o = 1; o < NWARPS; o <<= 1) {
            float y = __shfl_up_sync(0xFFFFFFFFu, w, o);
            if (lane >= o) w += y;
        }
        float woff = (wid > 0) ? __shfl_sync(0xFFFFFFFFu, w, wid - 1) : 0.0f;
        float off = woff + (s - p15);
        __syncthreads();                    // red[] reused below

        cb0.x = off + p00;  cb0.y = off + p01;  cb0.z = off + p02;  cb0.w = off + p03;
        cb1.x = off + p04;  cb1.y = off + p05;  cb1.z = off + p06;  cb1.w = off + p07;
        cb2.x = off + p08;  cb2.y = off + p09;  cb2.z = off + p10;  cb2.w = off + p11;
        cb3.x = off + p12;  cb3.y = off + p13;  cb3.z = off + p14;  cb3.w = off + p15;
    }

    // ---- main loop ----
    float total = 0.0f;
    int it = 0;

    while (row < D) {
        // prefetch row + 2G (2 iterations ahead)
        float4 u0, u1, u2, u3;
        const int  r2 = row + 2 * G;
        const bool uv = (r2 < D);
        if (uv) {
            const float4* p = xb + (size_t)r2 * (NN / 4) + t * VEC;
            u0 = p[0]; u1 = p[1]; u2 = p[2]; u3 = p[3];
        }

        // per-thread inclusive scan of current row's 16 elements
        float l00 = v0.x;
        float l01 = l00 + v0.y;
        float l02 = l01 + v0.z;
        float l03 = l02 + v0.w;
        float l04 = l03 + v1.x;
        float l05 = l04 + v1.y;
        float l06 = l05 + v1.z;
        float l07 = l06 + v1.w;
        float l08 = l07 + v2.x;
        float l09 = l08 + v2.y;
        float l10 = l09 + v2.z;
        float l11 = l10 + v2.w;
        float l12 = l11 + v3.x;
        float l13 = l12 + v3.y;
        float l14 = l13 + v3.z;
        float l15 = l14 + v3.w;

        // warp inclusive scan of thread totals
        float s = l15;
        #pragma unroll
        for (int o = 1; o < 32; o <<= 1) {
            float y = __shfl_up_sync(0xFFFFFFFFu, s, o);
            if (lane >= o) s += y;
        }
        if (lane == 31) ws[it & 1][wid] = s;
        __syncthreads();

        // every warp redundantly scans the warp sums (single barrier per row)
        float w = (lane < NWARPS) ? ws[it & 1][lane] : 0.0f;
        #pragma unroll
        for (int o = 1; o < NWARPS; o <<= 1) {
            float y = __shfl_up_sync(0xFFFFFFFFu, w, o);
            if (lane >= o) w += y;
        }
        float woff = (wid > 0) ? __shfl_sync(0xFFFFFFFFu, w, wid - 1) : 0.0f;
        float off = woff + (s - l15);       // exclusive prefix for this thread

        float acc;
        acc  = fabsf(off + l00 - cb0.x);
        acc += fabsf(off + l01 - cb0.y);
        acc += fabsf(off + l02 - cb0.z);
        acc += fabsf(off + l03 - cb0.w);
        acc += fabsf(off + l04 - cb1.x);
        acc += fabsf(off + l05 - cb1.y);
        acc += fabsf(off + l06 - cb1.z);
        acc += fabsf(off + l07 - cb1.w);
        acc += fabsf(off + l08 - cb2.x);
        acc += fabsf(off + l09 - cb2.y);
        acc += fabsf(off + l10 - cb2.z);
        acc += fabsf(off + l11 - cb2.w);
        acc += fabsf(off + l12 - cb3.x);
        acc += fabsf(off + l13 - cb3.y);
        acc += fabsf(off + l14 - cb3.z);
        if (t != THREADS - 1)               // exclude global index N-1
            acc += fabsf(off + l15 - cb3.w);

        total += acc;

        // rotate pipeline: v <- w <- u
        v0 = w0; v1 = w1; v2 = w2; v3 = w3;
        w0 = u0; w1 = u1; w2 = u2; w3 = u3;
        row += G; ++it;
    }

    // block reduction + one atomic per block
    #pragma unroll
    for (int o = 16; o > 0; o >>= 1)
        total += __shfl_down_sync(0xFFFFFFFFu, total, o);
    if (lane == 0) red[wid] = total;
    __syncthreads();
    if (wid == 0) {
        float v = (lane < NWARPS) ? red[lane] : 0.0f;
        #pragma unroll
        for (int o = NWARPS / 2; o > 0; o >>= 1)
            v += __shfl_down_sync(0xFFFFFFFFu, v, o);
        if (lane == 0) atomicAdd(out, v);
    }
}

// ---------------------------------------------------------------------------
extern "C" void kernel_launch(void* const* d_in, const int* in_sizes, int n_in,
                              void* d_out, int out_size)
{
    const float* x    = (const float*)d_in[0];   // [D, N] f32
    const float* bary = (const float*)d_in[1];   // [N] f32
    float* out = (float*)d_out;

    const int N = in_sizes[1];
    const int D = in_sizes[0] / N;
    (void)n_in; (void)out_size;

    // out[0] = 0 via D2D copy from a device-global zero (capturable, no alloc)
    void* zp = nullptr;
    cudaGetSymbolAddress(&zp, g_zero);
    cudaMemcpyAsync(out, zp, sizeof(float), cudaMemcpyDeviceToDevice, 0);
    // out[1..N] = bary
    cudaMemcpyAsync(out + 1, bary, (size_t)N * sizeof(float),
                    cudaMemcpyDeviceToDevice, 0);

    const int grid = (D < GBLOCKS) ? D : GBLOCKS;
    row_w1_kernel<<<grid, THREADS>>>(x, bary, out, D);
}

// round 8
// speedup vs baseline: 1.4951x; 1.0165x over previous
#include <cuda_runtime.h>
#include <cstdint>

#define NN      8192
#define THREADS 512
#define VEC     4                    // float4 loads per thread per row
#define NWARPS  (THREADS/32)
#define GBLOCKS 148                  // 1 block per SM, single wave

__device__ float g_zero = 0.0f;

// ---------------------------------------------------------------------------
// Persistent kernel, 1 block/SM. Processes TWO rows per iteration (row,
// row+G) so one barrier + one scan-latency shadow covers 64 KB of traffic.
// Next pair prefetched into registers one iteration ahead.
// ---------------------------------------------------------------------------
__global__ void __launch_bounds__(THREADS, 1)
row_w1_kernel(const float* __restrict__ x, const float* __restrict__ bary,
              float* __restrict__ out, int D)
{
    __shared__ float ws[2][2][NWARPS];   // [iter parity][row in pair][warp]
    __shared__ float red[NWARPS];

    const int t    = threadIdx.x;
    const int lane = t & 31;
    const int wid  = t >> 5;
    const int G    = gridDim.x;
    const int STEP = 2 * G;

    const float4* xb = reinterpret_cast<const float4*>(x);

    // ---- prologue: load pair (rowA, rowB) ----
    int rowA = blockIdx.x;               // grid <= D, so rowA < D
    int rowB = blockIdx.x + G;

    float4 a0, a1, a2, a3, b0, b1, b2, b3;
    {
        const float4* p = xb + (size_t)rowA * (NN / 4) + t * VEC;
        a0 = p[0]; a1 = p[1]; a2 = p[2]; a3 = p[3];
    }
    if (rowB < D) {
        const float4* p = xb + (size_t)rowB * (NN / 4) + t * VEC;
        b0 = p[0]; b1 = p[1]; b2 = p[2]; b3 = p[3];
    } else {
        b0 = b1 = b2 = b3 = make_float4(0.f, 0.f, 0.f, 0.f);
    }

    // ---- cb = cumsum(bary) for this thread's 16 columns (overlaps loads);
    //      block 0 also writes bary into out[1..N] ----
    float4 cb0, cb1, cb2, cb3;
    {
        const float4* bp = reinterpret_cast<const float4*>(bary) + t * VEC;
        float4 q0 = bp[0], q1 = bp[1], q2 = bp[2], q3 = bp[3];

        if (blockIdx.x == 0) {
            float* o = out + 1 + t * 16;
            o[0]=q0.x;  o[1]=q0.y;  o[2]=q0.z;  o[3]=q0.w;
            o[4]=q1.x;  o[5]=q1.y;  o[6]=q1.z;  o[7]=q1.w;
            o[8]=q2.x;  o[9]=q2.y;  o[10]=q2.z; o[11]=q2.w;
            o[12]=q3.x; o[13]=q3.y; o[14]=q3.z; o[15]=q3.w;
        }

        float p00 = q0.x;
        float p01 = p00 + q0.y;
        float p02 = p01 + q0.z;
        float p03 = p02 + q0.w;
        float p04 = p03 + q1.x;
        float p05 = p04 + q1.y;
        float p06 = p05 + q1.z;
        float p07 = p06 + q1.w;
        float p08 = p07 + q2.x;
        float p09 = p08 + q2.y;
        float p10 = p09 + q2.z;
        float p11 = p10 + q2.w;
        float p12 = p11 + q3.x;
        float p13 = p12 + q3.y;
        float p14 = p13 + q3.z;
        float p15 = p14 + q3.w;

        float s = p15;
        #pragma unroll
        for (int o = 1; o < 32; o <<= 1) {
            float y = __shfl_up_sync(0xFFFFFFFFu, s, o);
            if (lane >= o) s += y;
        }
        if (lane == 31) red[wid] = s;
        __syncthreads();
        float w = (lane < NWARPS) ? red[lane] : 0.0f;
        #pragma unroll
        for (int o = 1; o < NWARPS; o <<= 1) {
            float y = __shfl_up_sync(0xFFFFFFFFu, w, o);
            if (lane >= o) w += y;
        }
        float woff = (wid > 0) ? __shfl_sync(0xFFFFFFFFu, w, wid - 1) : 0.0f;
        float off = woff + (s - p15);
        __syncthreads();                 // red[] reused at the end

        cb0.x = off + p00;  cb0.y = off + p01;  cb0.z = off + p02;  cb0.w = off + p03;
        cb1.x = off + p04;  cb1.y = off + p05;  cb1.z = off + p06;  cb1.w = off + p07;
        cb2.x = off + p08;  cb2.y = off + p09;  cb2.z = off + p10;  cb2.w = off + p11;
        cb3.x = off + p12;  cb3.y = off + p13;  cb3.z = off + p14;  cb3.w = off + p15;
    }

    // ---- main loop: one pair of rows per iteration ----
    float total = 0.0f;
    int it = 0;

    while (rowA < D) {
        // prefetch next pair (one iteration ahead)
        const int nA = rowA + STEP;
        const int nB = rowB + STEP;
        float4 pa0, pa1, pa2, pa3, pb0, pb1, pb2, pb3;
        if (nA < D) {
            const float4* p = xb + (size_t)nA * (NN / 4) + t * VEC;
            pa0 = p[0]; pa1 = p[1]; pa2 = p[2]; pa3 = p[3];
        }
        if (nB < D) {
            const float4* p = xb + (size_t)nB * (NN / 4) + t * VEC;
            pb0 = p[0]; pb1 = p[1]; pb2 = p[2]; pb3 = p[3];
        }

        // -- per-thread inclusive scans (two independent chains) --
        float A00 = a0.x;
        float B00 = b0.x;
        float A01 = A00 + a0.y;   float B01 = B00 + b0.y;
        float A02 = A01 + a0.z;   float B02 = B01 + b0.z;
        float A03 = A02 + a0.w;   float B03 = B02 + b0.w;
        float A04 = A03 + a1.x;   float B04 = B03 + b1.x;
        float A05 = A04 + a1.y;   float B05 = B04 + b1.y;
        float A06 = A05 + a1.z;   float B06 = B05 + b1.z;
        float A07 = A06 + a1.w;   float B07 = B06 + b1.w;
        float A08 = A07 + a2.x;   float B08 = B07 + b2.x;
        float A09 = A08 + a2.y;   float B09 = B08 + b2.y;
        float A10 = A09 + a2.z;   float B10 = B09 + b2.z;
        float A11 = A10 + a2.w;   float B11 = B10 + b2.w;
        float A12 = A11 + a3.x;   float B12 = B11 + b3.x;
        float A13 = A12 + a3.y;   float B13 = B12 + b3.y;
        float A14 = A13 + a3.z;   float B14 = B13 + b3.z;
        float A15 = A14 + a3.w;   float B15 = B14 + b3.w;

        // -- warp inclusive scans of thread totals (interleaved) --
        float sA = A15, sB = B15;
        #pragma unroll
        for (int o = 1; o < 32; o <<= 1) {
            float yA = __shfl_up_sync(0xFFFFFFFFu, sA, o);
            float yB = __shfl_up_sync(0xFFFFFFFFu, sB, o);
            if (lane >= o) { sA += yA; sB += yB; }
        }
        if (lane == 31) {
            ws[it & 1][0][wid] = sA;
            ws[it & 1][1][wid] = sB;
        }
        __syncthreads();

        // -- redundant warp-sum scans (single barrier per pair) --
        float wA = (lane < NWARPS) ? ws[it & 1][0][lane] : 0.0f;
        float wB = (lane < NWARPS) ? ws[it & 1][1][lane] : 0.0f;
        #pragma unroll
        for (int o = 1; o < NWARPS; o <<= 1) {
            float yA = __shfl_up_sync(0xFFFFFFFFu, wA, o);
            float yB = __shfl_up_sync(0xFFFFFFFFu, wB, o);
            if (lane >= o) { wA += yA; wB += yB; }
        }
        float woA = (wid > 0) ? __shfl_sync(0xFFFFFFFFu, wA, wid - 1) : 0.0f;
        float woB = (wid > 0) ? __shfl_sync(0xFFFFFFFFu, wB, wid - 1) : 0.0f;
        float offA = woA + (sA - A15);
        float offB = woB + (sB - B15);

        // -- |ca - cb| accumulation, row A --
        float accA;
        accA  = fabsf(offA + A00 - cb0.x);
        accA += fabsf(offA + A01 - cb0.y);
        accA += fabsf(offA + A02 - cb0.z);
        accA += fabsf(offA + A03 - cb0.w);
        accA += fabsf(offA + A04 - cb1.x);
        accA += fabsf(offA + A05 - cb1.y);
        accA += fabsf(offA + A06 - cb1.z);
        accA += fabsf(offA + A07 - cb1.w);
        accA += fabsf(offA + A08 - cb2.x);
        accA += fabsf(offA + A09 - cb2.y);
        accA += fabsf(offA + A10 - cb2.z);
        accA += fabsf(offA + A11 - cb2.w);
        accA += fabsf(offA + A12 - cb3.x);
        accA += fabsf(offA + A13 - cb3.y);
        accA += fabsf(offA + A14 - cb3.z);
        if (t != THREADS - 1)
            accA += fabsf(offA + A15 - cb3.w);
        total += accA;

        // -- row B (only if valid) --
        if (rowB < D) {
            float accB;
            accB  = fabsf(offB + B00 - cb0.x);
            accB += fabsf(offB + B01 - cb0.y);
            accB += fabsf(offB + B02 - cb0.z);
            accB += fabsf(offB + B03 - cb0.w);
            accB += fabsf(offB + B04 - cb1.x);
            accB += fabsf(offB + B05 - cb1.y);
            accB += fabsf(offB + B06 - cb1.z);
            accB += fabsf(offB + B07 - cb1.w);
            accB += fabsf(offB + B08 - cb2.x);
            accB += fabsf(offB + B09 - cb2.y);
            accB += fabsf(offB + B10 - cb2.z);
            accB += fabsf(offB + B11 - cb2.w);
            accB += fabsf(offB + B12 - cb3.x);
            accB += fabsf(offB + B13 - cb3.y);
            accB += fabsf(offB + B14 - cb3.z);
            if (t != THREADS - 1)
                accB += fabsf(offB + B15 - cb3.w);
            total += accB;
        }

        // rotate pipeline
        a0 = pa0; a1 = pa1; a2 = pa2; a3 = pa3;
        b0 = pb0; b1 = pb1; b2 = pb2; b3 = pb3;
        rowA = nA; rowB = nB; ++it;
    }

    // ---- block reduction + one atomic per block ----
    #pragma unroll
    for (int o = 16; o > 0; o >>= 1)
        total += __shfl_down_sync(0xFFFFFFFFu, total, o);
    if (lane == 0) red[wid] = total;
    __syncthreads();
    if (wid == 0) {
        float v = (lane < NWARPS) ? red[lane] : 0.0f;
        #pragma unroll
        for (int o = NWARPS / 2; o > 0; o >>= 1)
            v += __shfl_down_sync(0xFFFFFFFFu, v, o);
        if (lane == 0) atomicAdd(out, v);
    }
}

// ---------------------------------------------------------------------------
extern "C" void kernel_launch(void* const* d_in, const int* in_sizes, int n_in,
                              void* d_out, int out_size)
{
    const float* x    = (const float*)d_in[0];   // [D, N] f32
    const float* bary = (const float*)d_in[1];   // [N] f32
    float* out = (float*)d_out;

    const int N = in_sizes[1];
    const int D = in_sizes[0] / N;
    (void)n_in; (void)out_size; (void)N;

    // out[0] = 0 via tiny D2D copy (stream-ordered before the kernel's atomics)
    void* zp = nullptr;
    cudaGetSymbolAddress(&zp, g_zero);
    cudaMemcpyAsync(out, zp, sizeof(float), cudaMemcpyDeviceToDevice, 0);

    const int grid = (D < GBLOCKS) ? D : GBLOCKS;
    row_w1_kernel<<<grid, THREADS>>>(x, bary, out, D);
}